// round 6
// baseline (speedup 1.0000x reference)
#include <cuda_runtime.h>

#define BATCH 256
#define CHAN  512
#define SEQL  2048
#define HID   32
#define FLEN  8

// Scratch (no allocations allowed in kernel_launch)
__device__ float g_stat[BATCH * CHAN];
__device__ float g_loss[BATCH];
__device__ int   g_cnt[BATCH];   // zero-init at load; each tail block resets
__device__ int   g_done;         // zero-init at load; final block resets

// ---------------------------------------------------------------------------
// Fused kernel: 16384 blocks x 256 threads. Block covers 8 rows (1 per warp)
// of sample b = blockIdx/64. The 64th block to finish a sample runs that
// sample's MLP + per-sample loss; the 256th sample-completion sums the loss.
// ---------------------------------------------------------------------------
__global__ void __launch_bounds__(256) fused_kernel(
    const float* __restrict__ x,
    const float* __restrict__ W1, const float* __restrict__ b1,
    const float* __restrict__ W2, const float* __restrict__ b2,
    const float* __restrict__ W3, const float* __restrict__ b3,
    float* __restrict__ out)
{
    const int tid  = threadIdx.x;
    const int warp = tid >> 5;          // 0..7
    const int lane = tid & 31;
    const int b    = blockIdx.x >> 6;   // sample this block belongs to

    // ---- Phase 1: max over L for this block's 8 rows ----------------------
    {
        const int row_idx = blockIdx.x * 8 + warp;       // global (b,c) row
        const float4* row = reinterpret_cast<const float4*>(x)
                          + (size_t)row_idx * (SEQL / 4);
        float m = -3.402823466e38f;
#pragma unroll
        for (int i = 0; i < (SEQL / 4) / 32; ++i) {
            float4 v = __ldcs(row + i * 32 + lane);
            m = fmaxf(m, fmaxf(fmaxf(v.x, v.y), fmaxf(v.z, v.w)));
        }
#pragma unroll
        for (int off = 16; off; off >>= 1)
            m = fmaxf(m, __shfl_xor_sync(0xffffffffu, m, off));
        if (lane == 0) g_stat[row_idx] = m;
    }
    __syncthreads();

    // ---- Elect per-sample tail block --------------------------------------
    __shared__ int s_tail;
    if (tid == 0) {
        __threadfence();                       // publish g_stat stores
        int old = atomicAdd(&g_cnt[b], 1);
        s_tail = (old == 63);
        if (old == 63) g_cnt[b] = 0;           // reset for next graph replay
    }
    __syncthreads();
    if (!s_tail) return;

    // ======================= Tail: MLP for sample b ========================
    __shared__ float4 s_stat4[CHAN / 4];
    __shared__ float  s_h1[HID];
    __shared__ float  s_h2[HID];
    __shared__ float  s_f[2 * FLEN];

    __threadfence();   // acquire: make all 64 blocks' g_stat stores visible

    // Load stat row (bypass L1 — written by other SMs)
    if (tid < CHAN / 4) {
        const float4* srow = reinterpret_cast<const float4*>(g_stat + b * CHAN);
        s_stat4[tid] = __ldcg(srow + tid);
    }
    __syncthreads();

    // h1[h] = relu(dot(stat, W1[h,:]) + b1[h]); warp w owns h = 4w..4w+3
    {
        float p[4];
#pragma unroll
        for (int j = 0; j < 4; ++j) {
            const int h = warp * 4 + j;
            const float4* w4 = reinterpret_cast<const float4*>(W1 + h * CHAN);
            float acc = 0.0f;
#pragma unroll
            for (int i = 0; i < 4; ++i) {
                float4 wv = __ldg(w4 + i * 32 + lane);
                float4 sv = s_stat4[i * 32 + lane];
                acc = fmaf(wv.x, sv.x, acc);
                acc = fmaf(wv.y, sv.y, acc);
                acc = fmaf(wv.z, sv.z, acc);
                acc = fmaf(wv.w, sv.w, acc);
            }
            p[j] = acc;
        }
#pragma unroll
        for (int off = 16; off; off >>= 1) {
#pragma unroll
            for (int j = 0; j < 4; ++j)
                p[j] += __shfl_xor_sync(0xffffffffu, p[j], off);
        }
        if (lane < 4) {
            const int h = warp * 4 + lane;
            s_h1[h] = fmaxf(p[lane] + b1[h], 0.0f);
        }
    }
    __syncthreads();

    // ---- tiny layers + loss on warp 0 -------------------------------------
    if (warp == 0) {
        const int t = lane;

        // h2 = relu(h1 @ W2^T + b2)
        {
            float acc = b2[t];
            const float* w = W2 + t * HID;
#pragma unroll
            for (int k = 0; k < HID; ++k)
                acc = fmaf(s_h1[k], __ldg(w + k), acc);
            s_h2[t] = fmaxf(acc, 0.0f);
        }
        __syncwarp();

        // filters = h2 @ W3^T + b3 (16 outputs)
        if (t < 2 * FLEN) {
            float acc = b3[t];
            const float* w = W3 + t * HID;
#pragma unroll
            for (int k = 0; k < HID; ++k)
                acc = fmaf(s_h2[k], __ldg(w + k), acc);
            s_f[t] = acc;
        }
        __syncwarp();

        // Outputs: out[0:2048] = lo, out[2048:4096] = hi
        if (t < FLEN) {
            out[b * FLEN + t]                = s_f[t];
            out[BATCH * FLEN + b * FLEN + t] = s_f[FLEN + t];
        }

        // Per-sample ortho loss (thread 0)
        if (t == 0) {
            float lo[FLEN], hi[FLEN];
            float nl = 0.0f, nh = 0.0f;
#pragma unroll
            for (int f = 0; f < FLEN; ++f) {
                lo[f] = s_f[f];
                hi[f] = s_f[FLEN + f];
                nl = fmaf(lo[f], lo[f], nl);
                nh = fmaf(hi[f], hi[f], nh);
            }
            const float inl = rsqrtf(nl);
            const float inh = rsqrtf(nh);
            float Ln[FLEN], Hn[FLEN];
#pragma unroll
            for (int f = 0; f < FLEN; ++f) { Ln[f] = lo[f] * inl; Hn[f] = hi[f] * inh; }

            float ps = 0.0f;
#pragma unroll
            for (int s = 1; s < FLEN; s += 2) {
                float dot = 0.0f;
#pragma unroll
                for (int f = 0; f < FLEN; ++f)
                    dot = fmaf(Ln[f], Ln[(f - s) & (FLEN - 1)], dot);
                ps += fabsf(dot);
            }
            float dLH = 0.0f, dLL = 0.0f, dHH = 0.0f;
#pragma unroll
            for (int f = 0; f < FLEN; ++f) {
                dLH = fmaf(Ln[f], Hn[f], dLH);
                dLL = fmaf(Ln[f], Ln[f], dLL);
                dHH = fmaf(Hn[f], Hn[f], dHH);
            }
            ps += fabsf(dLH) + fabsf(dLL - 1.0f) + fabsf(dHH - 1.0f);
            g_loss[b] = ps;
        }

        // ---- Elect final block; sum loss deterministically ----------------
        int done_old = 0;
        if (t == 0) {
            __threadfence();                   // publish g_loss[b]
            done_old = atomicAdd(&g_done, 1);
        }
        done_old = __shfl_sync(0xffffffffu, done_old, 0);
        if (done_old == BATCH - 1) {
            __threadfence();                   // acquire all g_loss stores
            // lane l sums g_loss[8l .. 8l+8), fixed order -> deterministic
            float v = 0.0f;
#pragma unroll
            for (int k = 0; k < 8; ++k)
                v += __ldcg(g_loss + t * 8 + k);
#pragma unroll
            for (int off = 16; off; off >>= 1)
                v += __shfl_xor_sync(0xffffffffu, v, off);
            if (t == 0) {
                out[2 * BATCH * FLEN] = v / (float)BATCH;
                g_done = 0;                    // reset for next graph replay
            }
        }
    }
}

// ---------------------------------------------------------------------------
extern "C" void kernel_launch(void* const* d_in, const int* in_sizes, int n_in,
                              void* d_out, int out_size) {
    const float* x  = (const float*)d_in[0];
    const float* W1 = (const float*)d_in[1];
    const float* b1 = (const float*)d_in[2];
    const float* W2 = (const float*)d_in[3];
    const float* b2 = (const float*)d_in[4];
    const float* W3 = (const float*)d_in[5];
    const float* b3 = (const float*)d_in[6];
    float* out = (float*)d_out;

    // 256*512 = 131072 rows, 8 rows/block -> 16384 blocks
    fused_kernel<<<(BATCH * CHAN) / 8, 256>>>(x, W1, b1, W2, b2, W3, b3, out);
}

// round 8
// speedup vs baseline: 1.0008x; 1.0008x over previous
#include <cuda_runtime.h>

#define BATCH 256
#define CHAN  512
#define SEQL  2048
#define HID   32
#define FLEN  8

// Scratch (no allocations allowed in kernel_launch)
__device__ float g_stat[BATCH * CHAN];
__device__ float g_loss[BATCH];
__device__ int   g_cnt[BATCH];   // zero at load; tail block resets each launch
__device__ int   g_done;         // zero at load; final block resets each launch

__device__ __forceinline__ int atom_add_release_gpu(int* p, int v) {
    int old;
    asm volatile("atom.release.gpu.global.add.s32 %0, [%1], %2;"
                 : "=r"(old) : "l"(p), "r"(v) : "memory");
    return old;
}
__device__ __forceinline__ int atom_add_acquire_gpu(int* p, int v) {
    int old;
    asm volatile("atom.acquire.gpu.global.add.s32 %0, [%1], %2;"
                 : "=r"(old) : "l"(p), "r"(v) : "memory");
    return old;
}

// ---------------------------------------------------------------------------
// Fused kernel: 16384 blocks x 256 threads. Block covers 8 rows (1 per warp)
// of sample b = blockIdx/64. The 64th block to publish (release atomic) runs
// that sample's MLP; the 256th sample-completion sums the loss.
// All cross-SM data goes through L2 (__stcg/__ldcg) so no L1 flush is needed.
// ---------------------------------------------------------------------------
__global__ void __launch_bounds__(256) fused_kernel(
    const float* __restrict__ x,
    const float* __restrict__ W1, const float* __restrict__ b1,
    const float* __restrict__ W2, const float* __restrict__ b2,
    const float* __restrict__ W3, const float* __restrict__ b3,
    float* __restrict__ out)
{
    const int tid  = threadIdx.x;
    const int warp = tid >> 5;          // 0..7
    const int lane = tid & 31;
    const int b    = blockIdx.x >> 6;   // sample this block belongs to

    // ---- Phase 1: max over L for this block's 8 rows ----------------------
    {
        const int row_idx = blockIdx.x * 8 + warp;       // global (b,c) row
        const float4* row = reinterpret_cast<const float4*>(x)
                          + (size_t)row_idx * (SEQL / 4);
        float m = -3.402823466e38f;
#pragma unroll
        for (int i = 0; i < (SEQL / 4) / 32; ++i) {
            float4 v = __ldcs(row + i * 32 + lane);
            m = fmaxf(m, fmaxf(fmaxf(v.x, v.y), fmaxf(v.z, v.w)));
        }
#pragma unroll
        for (int off = 16; off; off >>= 1)
            m = fmaxf(m, __shfl_xor_sync(0xffffffffu, m, off));
        if (lane == 0) __stcg(&g_stat[row_idx], m);      // straight to L2
    }
    __syncthreads();   // intra-block HB: all warps' stores precede tid0's atom

    // ---- Elect per-sample tail block (release atomic, no L1 flush) --------
    __shared__ int s_tail;
    if (tid == 0)
        s_tail = (atom_add_release_gpu(&g_cnt[b], 1) == 63);
    __syncthreads();
    if (!s_tail) return;

    // ======================= Tail: MLP for sample b ========================
    __shared__ float4 s_stat4[CHAN / 4];
    __shared__ float  s_h1[HID];
    __shared__ float  s_h2[HID];
    __shared__ float  s_f[2 * FLEN];

    if (tid == 0) {
        (void)atom_add_acquire_gpu(&g_cnt[b], 0);  // acquire: sync w/ 64 releases
        g_cnt[b] = 0;                              // reset for next replay
    }
    __syncthreads();

    // Load stat row from L2 (written via __stcg by other SMs)
    if (tid < CHAN / 4) {
        const float4* srow = reinterpret_cast<const float4*>(g_stat + b * CHAN);
        s_stat4[tid] = __ldcg(srow + tid);
    }
    __syncthreads();

    // h1[h] = relu(dot(stat, W1[h,:]) + b1[h]); warp w owns h = 4w..4w+3
    {
        float p[4];
#pragma unroll
        for (int j = 0; j < 4; ++j) {
            const int h = warp * 4 + j;
            const float4* w4 = reinterpret_cast<const float4*>(W1 + h * CHAN);
            float acc = 0.0f;
#pragma unroll
            for (int i = 0; i < 4; ++i) {
                float4 wv = __ldg(w4 + i * 32 + lane);
                float4 sv = s_stat4[i * 32 + lane];
                acc = fmaf(wv.x, sv.x, acc);
                acc = fmaf(wv.y, sv.y, acc);
                acc = fmaf(wv.z, sv.z, acc);
                acc = fmaf(wv.w, sv.w, acc);
            }
            p[j] = acc;
        }
#pragma unroll
        for (int off = 16; off; off >>= 1) {
#pragma unroll
            for (int j = 0; j < 4; ++j)
                p[j] += __shfl_xor_sync(0xffffffffu, p[j], off);
        }
        if (lane < 4) {
            const int h = warp * 4 + lane;
            s_h1[h] = fmaxf(p[lane] + b1[h], 0.0f);
        }
    }
    __syncthreads();

    // ---- tiny layers + loss on warp 0 -------------------------------------
    if (warp == 0) {
        const int t = lane;

        // h2 = relu(h1 @ W2^T + b2)
        {
            float acc = b2[t];
            const float* w = W2 + t * HID;
#pragma unroll
            for (int k = 0; k < HID; ++k)
                acc = fmaf(s_h1[k], __ldg(w + k), acc);
            s_h2[t] = fmaxf(acc, 0.0f);
        }
        __syncwarp();

        // filters = h2 @ W3^T + b3 (16 outputs)
        if (t < 2 * FLEN) {
            float acc = b3[t];
            const float* w = W3 + t * HID;
#pragma unroll
            for (int k = 0; k < HID; ++k)
                acc = fmaf(s_h2[k], __ldg(w + k), acc);
            s_f[t] = acc;
        }
        __syncwarp();

        // Outputs: out[0:2048] = lo, out[2048:4096] = hi
        if (t < FLEN) {
            out[b * FLEN + t]                = s_f[t];
            out[BATCH * FLEN + b * FLEN + t] = s_f[FLEN + t];
        }

        // Per-sample ortho loss (thread 0)
        if (t == 0) {
            float lo[FLEN], hi[FLEN];
            float nl = 0.0f, nh = 0.0f;
#pragma unroll
            for (int f = 0; f < FLEN; ++f) {
                lo[f] = s_f[f];
                hi[f] = s_f[FLEN + f];
                nl = fmaf(lo[f], lo[f], nl);
                nh = fmaf(hi[f], hi[f], nh);
            }
            const float inl = rsqrtf(nl);
            const float inh = rsqrtf(nh);
            float Ln[FLEN], Hn[FLEN];
#pragma unroll
            for (int f = 0; f < FLEN; ++f) { Ln[f] = lo[f] * inl; Hn[f] = hi[f] * inh; }

            float ps = 0.0f;
#pragma unroll
            for (int s = 1; s < FLEN; s += 2) {
                float dot = 0.0f;
#pragma unroll
                for (int f = 0; f < FLEN; ++f)
                    dot = fmaf(Ln[f], Ln[(f - s) & (FLEN - 1)], dot);
                ps += fabsf(dot);
            }
            float dLH = 0.0f, dLL = 0.0f, dHH = 0.0f;
#pragma unroll
            for (int f = 0; f < FLEN; ++f) {
                dLH = fmaf(Ln[f], Hn[f], dLH);
                dLL = fmaf(Ln[f], Ln[f], dLL);
                dHH = fmaf(Hn[f], Hn[f], dHH);
            }
            ps += fabsf(dLH) + fabsf(dLL - 1.0f) + fabsf(dHH - 1.0f);
            __stcg(&g_loss[b], ps);            // publish via L2
        }

        // ---- Elect final block; sum loss deterministically ----------------
        int done_old = 0;
        if (t == 0)
            done_old = atom_add_release_gpu(&g_done, 1);   // orders g_loss[b]
        done_old = __shfl_sync(0xffffffffu, done_old, 0);
        if (done_old == BATCH - 1) {
            if (t == 0) (void)atom_add_acquire_gpu(&g_done, 0);
            __syncwarp();
            // lane t sums g_loss[8t .. 8t+8), fixed order -> deterministic
            float v = 0.0f;
#pragma unroll
            for (int k = 0; k < 8; ++k)
                v += __ldcg(g_loss + t * 8 + k);
#pragma unroll
            for (int off = 16; off; off >>= 1)
                v += __shfl_xor_sync(0xffffffffu, v, off);
            if (t == 0) {
                out[2 * BATCH * FLEN] = v / (float)BATCH;
                g_done = 0;                    // reset for next replay
            }
        }
    }
}

// ---------------------------------------------------------------------------
extern "C" void kernel_launch(void* const* d_in, const int* in_sizes, int n_in,
                              void* d_out, int out_size) {
    const float* x  = (const float*)d_in[0];
    const float* W1 = (const float*)d_in[1];
    const float* b1 = (const float*)d_in[2];
    const float* W2 = (const float*)d_in[3];
    const float* b2 = (const float*)d_in[4];
    const float* W3 = (const float*)d_in[5];
    const float* b3 = (const float*)d_in[6];
    float* out = (float*)d_out;

    // 256*512 = 131072 rows, 8 rows/block -> 16384 blocks
    fused_kernel<<<(BATCH * CHAN) / 8, 256>>>(x, W1, b1, W2, b2, W3, b3, out);
}

// round 13
// speedup vs baseline: 1.0088x; 1.0079x over previous
#include <cuda_runtime.h>

#define BATCH 256
#define CHAN  512
#define SEQL  2048
#define HID   32
#define FLEN  8

// Scratch (no allocations allowed in kernel_launch)
__device__ float g_stat[BATCH * CHAN];
__device__ float g_loss[BATCH];
__device__ int   g_cnt[BATCH];   // zero at load; tail block resets each launch
__device__ int   g_done;         // zero at load; final block resets each launch

__device__ __forceinline__ int atom_add_release_gpu(int* p, int v) {
    int old;
    asm volatile("atom.release.gpu.global.add.s32 %0, [%1], %2;"
                 : "=r"(old) : "l"(p), "r"(v) : "memory");
    return old;
}
__device__ __forceinline__ int atom_add_acquire_gpu(int* p, int v) {
    int old;
    asm volatile("atom.acquire.gpu.global.add.s32 %0, [%1], %2;"
                 : "=r"(old) : "l"(p), "r"(v) : "memory");
    return old;
}

// ---------------------------------------------------------------------------
// Fused kernel: 16384 blocks x 256 threads. Block covers 8 rows (1 per warp)
// of sample b = blockIdx/64. The 64th block to publish (release atomic) runs
// that sample's MLP; the 256th sample-completion sums the loss.
// __launch_bounds__(256, 8) pins regs<=32 so the streaming phase keeps
// 8 blocks/SM (100% occ); the rare tail path may spill, which is fine.
// ---------------------------------------------------------------------------
__global__ void __launch_bounds__(256, 8) fused_kernel(
    const float* __restrict__ x,
    const float* __restrict__ W1, const float* __restrict__ b1,
    const float* __restrict__ W2, const float* __restrict__ b2,
    const float* __restrict__ W3, const float* __restrict__ b3,
    float* __restrict__ out)
{
    const int tid  = threadIdx.x;
    const int warp = tid >> 5;          // 0..7
    const int lane = tid & 31;
    const int b    = blockIdx.x >> 6;   // sample this block belongs to

    // ---- Phase 1: max over L for this block's 8 rows ----------------------
    {
        const int row_idx = blockIdx.x * 8 + warp;       // global (b,c) row
        const float4* row = reinterpret_cast<const float4*>(x)
                          + (size_t)row_idx * (SEQL / 4);
        float m = -3.402823466e38f;
#pragma unroll
        for (int i = 0; i < (SEQL / 4) / 32; ++i) {
            float4 v = __ldcs(row + i * 32 + lane);
            m = fmaxf(m, fmaxf(fmaxf(v.x, v.y), fmaxf(v.z, v.w)));
        }
#pragma unroll
        for (int off = 16; off; off >>= 1)
            m = fmaxf(m, __shfl_xor_sync(0xffffffffu, m, off));
        if (lane == 0) __stcg(&g_stat[row_idx], m);      // straight to L2
    }
    __syncthreads();   // intra-block HB: all warps' stores precede tid0's atom

    // ---- Elect per-sample tail block (release atomic) ---------------------
    __shared__ int s_tail;
    if (tid == 0)
        s_tail = (atom_add_release_gpu(&g_cnt[b], 1) == 63);
    __syncthreads();
    if (!s_tail) return;

    // ======================= Tail: MLP for sample b ========================
    __shared__ float4 s_stat4[CHAN / 4];
    __shared__ float  s_h1[HID];
    __shared__ float  s_h2[HID];
    __shared__ float  s_f[2 * FLEN];

    if (tid == 0) {
        (void)atom_add_acquire_gpu(&g_cnt[b], 0);  // acquire: sync w/ 64 releases
        g_cnt[b] = 0;                              // reset for next replay
    }
    __syncthreads();

    // Load stat row from L2 (written via __stcg by other SMs)
    if (tid < CHAN / 4) {
        const float4* srow = reinterpret_cast<const float4*>(g_stat + b * CHAN);
        s_stat4[tid] = __ldcg(srow + tid);
    }
    __syncthreads();

    // h1[h] = relu(dot(stat, W1[h,:]) + b1[h]); warp w owns h = 4w..4w+3
    {
        float p[4];
#pragma unroll
        for (int j = 0; j < 4; ++j) {
            const int h = warp * 4 + j;
            const float4* w4 = reinterpret_cast<const float4*>(W1 + h * CHAN);
            float acc = 0.0f;
#pragma unroll
            for (int i = 0; i < 4; ++i) {
                float4 wv = __ldg(w4 + i * 32 + lane);
                float4 sv = s_stat4[i * 32 + lane];
                acc = fmaf(wv.x, sv.x, acc);
                acc = fmaf(wv.y, sv.y, acc);
                acc = fmaf(wv.z, sv.z, acc);
                acc = fmaf(wv.w, sv.w, acc);
            }
            p[j] = acc;
        }
#pragma unroll
        for (int off = 16; off; off >>= 1) {
#pragma unroll
            for (int j = 0; j < 4; ++j)
                p[j] += __shfl_xor_sync(0xffffffffu, p[j], off);
        }
        if (lane < 4) {
            const int h = warp * 4 + lane;
            s_h1[h] = fmaxf(p[lane] + b1[h], 0.0f);
        }
    }
    __syncthreads();

    // ---- tiny layers + loss on warp 0 -------------------------------------
    if (warp == 0) {
        const int t = lane;

        // h2 = relu(h1 @ W2^T + b2)
        {
            float acc = b2[t];
            const float* w = W2 + t * HID;
#pragma unroll
            for (int k = 0; k < HID; ++k)
                acc = fmaf(s_h1[k], __ldg(w + k), acc);
            s_h2[t] = fmaxf(acc, 0.0f);
        }
        __syncwarp();

        // filters = h2 @ W3^T + b3 (16 outputs)
        if (t < 2 * FLEN) {
            float acc = b3[t];
            const float* w = W3 + t * HID;
#pragma unroll
            for (int k = 0; k < HID; ++k)
                acc = fmaf(s_h2[k], __ldg(w + k), acc);
            s_f[t] = acc;
        }
        __syncwarp();

        // Outputs: out[0:2048] = lo, out[2048:4096] = hi
        if (t < FLEN) {
            out[b * FLEN + t]                = s_f[t];
            out[BATCH * FLEN + b * FLEN + t] = s_f[FLEN + t];
        }

        // Per-sample ortho loss (thread 0) — read filters from smem to keep
        // register pressure off the streaming path.
        if (t == 0) {
            float nl = 0.0f, nh = 0.0f;
#pragma unroll
            for (int f = 0; f < FLEN; ++f) {
                nl = fmaf(s_f[f], s_f[f], nl);
                nh = fmaf(s_f[FLEN + f], s_f[FLEN + f], nh);
            }
            const float inl = rsqrtf(nl);
            const float inh = rsqrtf(nh);

            float ps = 0.0f;
#pragma unroll
            for (int s = 1; s < FLEN; s += 2) {
                float dot = 0.0f;
#pragma unroll
                for (int f = 0; f < FLEN; ++f)
                    dot = fmaf(s_f[f], s_f[(f - s) & (FLEN - 1)], dot);
                ps += fabsf(dot * inl * inl);
            }
            float dLH = 0.0f, dLL = 0.0f, dHH = 0.0f;
#pragma unroll
            for (int f = 0; f < FLEN; ++f) {
                dLH = fmaf(s_f[f], s_f[FLEN + f], dLH);
                dLL = fmaf(s_f[f], s_f[f], dLL);
                dHH = fmaf(s_f[FLEN + f], s_f[FLEN + f], dHH);
            }
            ps += fabsf(dLH * inl * inh)
                + fabsf(dLL * inl * inl - 1.0f)
                + fabsf(dHH * inh * inh - 1.0f);
            __stcg(&g_loss[b], ps);            // publish via L2
        }

        // ---- Elect final block; sum loss deterministically ----------------
        int done_old = 0;
        if (t == 0)
            done_old = atom_add_release_gpu(&g_done, 1);   // orders g_loss[b]
        done_old = __shfl_sync(0xffffffffu, done_old, 0);
        if (done_old == BATCH - 1) {
            if (t == 0) (void)atom_add_acquire_gpu(&g_done, 0);
            __syncwarp();
            // lane t loads g_loss[8t .. 8t+8) up-front (MLP=8), then sums in
            // fixed order -> deterministic.
            float v0 = __ldcg(g_loss + t * 8 + 0);
            float v1 = __ldcg(g_loss + t * 8 + 1);
            float v2 = __ldcg(g_loss + t * 8 + 2);
            float v3 = __ldcg(g_loss + t * 8 + 3);
            float v4 = __ldcg(g_loss + t * 8 + 4);
            float v5 = __ldcg(g_loss + t * 8 + 5);
            float v6 = __ldcg(g_loss + t * 8 + 6);
            float v7 = __ldcg(g_loss + t * 8 + 7);
            float v = ((((((v0 + v1) + v2) + v3) + v4) + v5) + v6) + v7;
#pragma unroll
            for (int off = 16; off; off >>= 1)
                v += __shfl_xor_sync(0xffffffffu, v, off);
            if (t == 0) {
                out[2 * BATCH * FLEN] = v / (float)BATCH;
                g_done = 0;                    // reset for next replay
            }
        }
    }
}

// ---------------------------------------------------------------------------
extern "C" void kernel_launch(void* const* d_in, const int* in_sizes, int n_in,
                              void* d_out, int out_size) {
    const float* x  = (const float*)d_in[0];
    const float* W1 = (const float*)d_in[1];
    const float* b1 = (const float*)d_in[2];
    const float* W2 = (const float*)d_in[3];
    const float* b2 = (const float*)d_in[4];
    const float* W3 = (const float*)d_in[5];
    const float* b3 = (const float*)d_in[6];
    float* out = (float*)d_out;

    // 256*512 = 131072 rows, 8 rows/block -> 16384 blocks
    fused_kernel<<<(BATCH * CHAN) / 8, 256>>>(x, W1, b1, W2, b2, W3, b3, out);
}